// round 3
// baseline (speedup 1.0000x reference)
#include <cuda_runtime.h>

// B=32, L=1024, D=64.
// Algebraic collapse (verified R1, rel_err 1.4e-7):
//   out[b,0,:] = sum_l x[b,l,:] / 1024 ;  out[b,1:,:] = 0.
//   W1,b1,W2,b2,timestamp are dead inputs.
//
// Layout notes:
//   row  = 64 floats = 16 float4 = 256 B = two 128 B lines.
//   Reduction block (bid < 64) = (batch b, half h): owns the 128 B slice
//   [h*8, h*8+8) float4 of every row. Warp access = 4 rows x 128 B
//   contiguous -> exactly 4 full lines per LDG.128 (no wasted sectors).
//   Zero blocks (bid >= 64) cover all of out except row 0 of each batch
//   (disjoint from reduction writes -> no ordering needed).

#define RED_BLOCKS   64
#define ZERO_BLOCKS  1120
#define TOTAL_BLOCKS (RED_BLOCKS + ZERO_BLOCKS)

#define F4_PER_BATCH 16384u   // 1024 rows * 16 float4
#define F4_PER_ROW   16u
#define N_F4_TOTAL   (32u * F4_PER_BATCH)

__device__ __forceinline__ void f4add(float4& a, const float4& b) {
    a.x += b.x; a.y += b.y; a.z += b.z; a.w += b.w;
}

__device__ __forceinline__ float4 f4shfl_down(float4 v, int delta) {
    v.x = __shfl_down_sync(0xffffffffu, v.x, delta);
    v.y = __shfl_down_sync(0xffffffffu, v.y, delta);
    v.z = __shfl_down_sync(0xffffffffu, v.z, delta);
    v.w = __shfl_down_sync(0xffffffffu, v.w, delta);
    return v;
}

__global__ void __launch_bounds__(256) um_fused_kernel(
    const float4* __restrict__ x4, float4* __restrict__ out4)
{
    const int bid = blockIdx.x;
    const int tid = threadIdx.x;

    if (bid < RED_BLOCKS) {
        // ---------------- reduction: (b, h) owns 8 float4 columns ----------
        const int b  = bid >> 1;
        const int h  = bid & 1;
        const int c  = tid & 7;        // float4 column within the 128B slice
        const int lg = tid >> 3;       // 0..31: row group

        const float4* base = x4 + (size_t)b * F4_PER_BATCH + h * 8 + c;

        // 32 independent loads, 4 accumulators for ILP
        float4 s0 = make_float4(0,0,0,0), s1 = s0, s2 = s0, s3 = s0;
        #pragma unroll
        for (int j = 0; j < 32; j += 4) {
            float4 v0 = base[(size_t)(lg + 32*(j+0)) * F4_PER_ROW];
            float4 v1 = base[(size_t)(lg + 32*(j+1)) * F4_PER_ROW];
            float4 v2 = base[(size_t)(lg + 32*(j+2)) * F4_PER_ROW];
            float4 v3 = base[(size_t)(lg + 32*(j+3)) * F4_PER_ROW];
            f4add(s0, v0); f4add(s1, v1); f4add(s2, v2); f4add(s3, v3);
        }
        f4add(s0, s1); f4add(s2, s3); f4add(s0, s2);

        // warp reduce: lanes with equal (lane & 7) share a column.
        f4add(s0, f4shfl_down(s0, 16));
        f4add(s0, f4shfl_down(s0, 8));

        __shared__ float4 sm[8][8];    // [warp][column]
        const int lane = tid & 31;
        const int wid  = tid >> 5;
        if (lane < 8) sm[wid][lane] = s0;
        __syncthreads();

        if (tid < 8) {
            float4 t = sm[0][tid];
            #pragma unroll
            for (int w = 1; w < 8; ++w) f4add(t, sm[w][tid]);
            const float inv = 1.0f / 1024.0f;
            t.x *= inv; t.y *= inv; t.z *= inv; t.w *= inv;
            out4[(size_t)b * F4_PER_BATCH + h * 8 + tid] = t;
        }
    } else {
        // ---------------- zeroing: everything except row 0 -----------------
        const unsigned zid  = (unsigned)(bid - RED_BLOCKS);
        const unsigned step = ZERO_BLOCKS * 256u;
        const float4 z = make_float4(0.f, 0.f, 0.f, 0.f);
        #pragma unroll 2
        for (unsigned i = zid * 256u + (unsigned)tid; i < N_F4_TOTAL; i += step) {
            if ((i & (F4_PER_BATCH - 1u)) >= F4_PER_ROW)   // skip row 0
                out4[i] = z;
        }
    }
}

extern "C" void kernel_launch(void* const* d_in, const int* in_sizes, int n_in,
                              void* d_out, int out_size) {
    const float4* x4 = (const float4*)d_in[0];   // user_embedding [32,1024,64]
    float4* out4 = (float4*)d_out;               // [32,1024,64]
    um_fused_kernel<<<TOTAL_BLOCKS, 256>>>(x4, out4);
}

// round 4
// speedup vs baseline: 1.3430x; 1.3430x over previous
#include <cuda_runtime.h>

// B=32, L=1024, D=64.
// Algebraic collapse (verified R1-R3, rel_err ~1.4e-7):
//   out[b,0,:] = sum_l x[b,l,:] / 1024 ;  out[b,1:,:] = 0.
//   W1,b1,W2,b2,timestamp are dead inputs.
//
// R4: concurrency-first. 64 reduction blocks x 512 threads (16 warps),
// 16 loads/thread in 8-deep batches (MLP~8). 232 zero blocks x 512 threads.
// Grid 296 x 512 = 2 CTAs/SM -> single wave.

#define RED_BLOCKS   64
#define ZERO_BLOCKS  232
#define TOTAL_BLOCKS (RED_BLOCKS + ZERO_BLOCKS)
#define NTHREADS     512

#define F4_PER_BATCH 16384u   // 1024 rows * 16 float4
#define F4_PER_ROW   16u
#define N_F4_TOTAL   (32u * F4_PER_BATCH)

__device__ __forceinline__ void f4add(float4& a, const float4& b) {
    a.x += b.x; a.y += b.y; a.z += b.z; a.w += b.w;
}

__device__ __forceinline__ float4 f4shfl_down(float4 v, int delta) {
    v.x = __shfl_down_sync(0xffffffffu, v.x, delta);
    v.y = __shfl_down_sync(0xffffffffu, v.y, delta);
    v.z = __shfl_down_sync(0xffffffffu, v.z, delta);
    v.w = __shfl_down_sync(0xffffffffu, v.w, delta);
    return v;
}

__global__ void __launch_bounds__(NTHREADS) um_fused_kernel(
    const float4* __restrict__ x4, float4* __restrict__ out4)
{
    const int bid = blockIdx.x;
    const int tid = threadIdx.x;

    if (bid < RED_BLOCKS) {
        // ---- reduction: (batch b, half h) owns a 128B column slice --------
        const int b  = bid >> 1;
        const int h  = bid & 1;
        const int c  = tid & 7;        // float4 column within the slice
        const int lg = tid >> 3;       // 0..63: row group

        const float4* base = x4 + (size_t)b * F4_PER_BATCH + h * 8 + c;

        // 16 loads/thread, two fully-independent batches of 8 (MLP ~8)
        float4 a0 = make_float4(0,0,0,0), a1 = a0, a2 = a0, a3 = a0;
        float4 a4 = a0, a5 = a0, a6 = a0, a7 = a0;
        #pragma unroll
        for (int j = 0; j < 16; j += 8) {
            float4 v0 = base[(size_t)(lg + 64*(j+0)) * F4_PER_ROW];
            float4 v1 = base[(size_t)(lg + 64*(j+1)) * F4_PER_ROW];
            float4 v2 = base[(size_t)(lg + 64*(j+2)) * F4_PER_ROW];
            float4 v3 = base[(size_t)(lg + 64*(j+3)) * F4_PER_ROW];
            float4 v4 = base[(size_t)(lg + 64*(j+4)) * F4_PER_ROW];
            float4 v5 = base[(size_t)(lg + 64*(j+5)) * F4_PER_ROW];
            float4 v6 = base[(size_t)(lg + 64*(j+6)) * F4_PER_ROW];
            float4 v7 = base[(size_t)(lg + 64*(j+7)) * F4_PER_ROW];
            f4add(a0, v0); f4add(a1, v1); f4add(a2, v2); f4add(a3, v3);
            f4add(a4, v4); f4add(a5, v5); f4add(a6, v6); f4add(a7, v7);
        }
        f4add(a0, a1); f4add(a2, a3); f4add(a4, a5); f4add(a6, a7);
        f4add(a0, a2); f4add(a4, a6); f4add(a0, a4);

        // warp reduce: lanes with equal (lane & 7) share a column slice.
        f4add(a0, f4shfl_down(a0, 16));
        f4add(a0, f4shfl_down(a0, 8));

        __shared__ float4 sm[16][8];   // [warp][column]
        const int lane = tid & 31;
        const int wid  = tid >> 5;
        if (lane < 8) sm[wid][lane] = a0;
        __syncthreads();

        if (tid < 8) {
            float4 t = sm[0][tid];
            #pragma unroll
            for (int w = 1; w < 16; ++w) f4add(t, sm[w][tid]);
            const float inv = 1.0f / 1024.0f;
            t.x *= inv; t.y *= inv; t.z *= inv; t.w *= inv;
            out4[(size_t)b * F4_PER_BATCH + h * 8 + tid] = t;
        }
    } else {
        // ---- zeroing: everything except row 0 of each batch ---------------
        const unsigned zid  = (unsigned)(bid - RED_BLOCKS);
        const unsigned step = ZERO_BLOCKS * (unsigned)NTHREADS;
        const float4 z = make_float4(0.f, 0.f, 0.f, 0.f);
        for (unsigned i = zid * (unsigned)NTHREADS + (unsigned)tid;
             i < N_F4_TOTAL; i += step) {
            if ((i & (F4_PER_BATCH - 1u)) >= F4_PER_ROW)   // skip row 0
                out4[i] = z;
        }
    }
}

extern "C" void kernel_launch(void* const* d_in, const int* in_sizes, int n_in,
                              void* d_out, int out_size) {
    const float4* x4 = (const float4*)d_in[0];   // user_embedding [32,1024,64]
    float4* out4 = (float4*)d_out;               // [32,1024,64]
    um_fused_kernel<<<TOTAL_BLOCKS, NTHREADS>>>(x4, out4);
}